// round 1
// baseline (speedup 1.0000x reference)
#include <cuda_runtime.h>
#include <cuda_bf16.h>

// GraphSage_89781996355909 — exact algebraic collapse.
//
// The reference's final op is jax.nn.softmax(x @ W5 + b5, axis=-1) where the
// last axis has dimension 1 (W5: [8,1]). Softmax over a single element is
// identically 1.0 for any finite logit: exp(x - max) / sum = exp(0)/exp(0) = 1.
// Every upstream value is finite (Gaussian inputs, uniform dif matrices,
// GEMM/ReLU/l2-normalize chains — no overflow path), so the entire forward
// pass reduces to writing 1.0f to all out_size (= 512) output elements,
// independent of every input tensor. This holds for all inputs, not just the
// benchmark seed, so it is exactly correct per the reference semantics.
//
// Deterministic, graph-capturable, allocation-free: a single tiny kernel.

__global__ void GraphSage_89781996355909_kernel(float* __restrict__ out, int n) {
    int i = blockIdx.x * blockDim.x + threadIdx.x;
    if (i < n) out[i] = 1.0f;
}

extern "C" void kernel_launch(void* const* d_in, const int* in_sizes, int n_in,
                              void* d_out, int out_size) {
    (void)d_in; (void)in_sizes; (void)n_in;
    float* out = (float*)d_out;
    int threads = 256;
    int blocks = (out_size + threads - 1) / threads;
    if (blocks < 1) blocks = 1;
    GraphSage_89781996355909_kernel<<<blocks, threads>>>(out, out_size);
}

// round 3
// speedup vs baseline: 1.4931x; 1.4931x over previous
#include <cuda_runtime.h>
#include <cuda_bf16.h>
#include <cstdint>

// GraphSage_89781996355909 — exact algebraic collapse (see R1 analysis).
//
// Final reference op: jax.nn.softmax(x @ W5 + b5, axis=-1) with last-axis
// dim 1 (W5: [8,1]). Single-element softmax == 1.0 for any finite logit, and
// all upstream values are finite, so output == ones(512) for ALL inputs.
//
// R3: same as R2 (single CTA, vectorized STG.128: 512 floats = 128 float4
// stores from one 128-thread block) with the missing <cstdint> include fixed.
// Scalar tail path kept for generality (unused at 512).

__global__ void GraphSage_89781996355909_fill4(float4* __restrict__ out4, int n4) {
    int i = threadIdx.x + blockIdx.x * blockDim.x;
    if (i < n4) out4[i] = make_float4(1.0f, 1.0f, 1.0f, 1.0f);
}

__global__ void GraphSage_89781996355909_fill1(float* __restrict__ out, int n) {
    int i = threadIdx.x + blockIdx.x * blockDim.x;
    if (i < n) out[i] = 1.0f;
}

extern "C" void kernel_launch(void* const* d_in, const int* in_sizes, int n_in,
                              void* d_out, int out_size) {
    (void)d_in; (void)in_sizes; (void)n_in;
    if ((out_size & 3) == 0 && (((unsigned long long)d_out) & 15ull) == 0) {
        int n4 = out_size >> 2;              // 512 -> 128
        int threads = (n4 < 128) ? (n4 > 0 ? n4 : 1) : 128;
        int blocks = (n4 + threads - 1) / threads;
        if (blocks < 1) blocks = 1;
        GraphSage_89781996355909_fill4<<<blocks, threads>>>((float4*)d_out, n4);
    } else {
        int threads = 256;
        int blocks = (out_size + threads - 1) / threads;
        if (blocks < 1) blocks = 1;
        GraphSage_89781996355909_fill1<<<blocks, threads>>>((float*)d_out, out_size);
    }
}